// round 16
// baseline (speedup 1.0000x reference)
#include <cuda_runtime.h>
#include <math.h>

#define NB 256      // batch / steps
#define ND 512      // D
#define NH 2048     // H
#define NS 32768    // slots
#define RSPLIT 32
#define CMAX 4096
#define CCAP 1024
#define RC 8192
#define SEG (NS / 256)   // 128 elements per thread in prep scan

// ---------------- static device scratch ----------------
__device__ float g_K[NB * ND];
__device__ float g_WV[NB * ND];
__device__ float g_G[NB * NB];
__device__ float g_E[NB * NS];
__device__ float g_m[NB];
__device__ float g_part[RSPLIT * NB * ND];
__device__ int   g_slots[NB];
__device__ float g_merged[NB * 2 * ND];
__device__ float g_H1[NB * NH];
__device__ unsigned long long g_cand[(size_t)NB * CMAX];
__device__ int g_cand_n[NB];
__device__ unsigned int g_rcand[(size_t)NB * RC];
__device__ int g_rcand_n[NB];

__device__ __forceinline__ unsigned int fkey(float f) {
    unsigned int u = __float_as_uint(f);
    return u ^ (((unsigned int)((int)u >> 31)) | 0x80000000u);
}

__device__ __forceinline__ void ffma2(unsigned long long& d, unsigned long long a,
                                      unsigned long long b) {
    asm("fma.rn.f32x2 %0, %1, %2, %0;" : "+l"(d) : "l"(a), "l"(b));
}
__device__ __forceinline__ unsigned long long bcast2(float x) {
    unsigned long long r;
    unsigned int u = __float_as_uint(x);
    asm("mov.b64 %0, {%1, %1};" : "=l"(r) : "r"(u));
    return r;
}
__device__ __forceinline__ float2 unpack2(unsigned long long v) {
    float2 f;
    asm("mov.b64 {%0, %1}, %2;" : "=f"(f.x), "=f"(f.y) : "l"(v));
    return f;
}

// ---------------- fused projection split-K: z<4 -> K partials, z>=4 -> WV ----------------
__global__ void __launch_bounds__(256) proj_split(
    const float* __restrict__ S, const float* __restrict__ Wk,
    const float* __restrict__ Wv, float* __restrict__ outP)
{
    __shared__ __align__(16) float As[16][68];
    __shared__ __align__(16) float Bs[16][68];
    const int tid = threadIdx.x;
    const int tx = tid & 15, ty = tid >> 4;
    const int bm0 = blockIdx.y * 64, bn0 = blockIdx.x * 64;
    const int z = blockIdx.z;
    const int kbase = (z & 3) * 128;
    const float* B = (z < 4) ? Wk : Wv;
    const int lr = tid >> 2;
    const int lq = (tid & 3) * 4;
    const float* Ap = S + (size_t)(bm0 + lr) * ND + kbase + lq;
    const float* Bp = B + (size_t)(bn0 + lr) * ND + kbase + lq;
    unsigned long long acc2[4][2] = {};
    for (int k0 = 0; k0 < 128; k0 += 16) {
        float4 av = *(const float4*)(Ap + k0);
        float4 bv = *(const float4*)(Bp + k0);
        __syncthreads();
        As[lq + 0][lr] = av.x; As[lq + 1][lr] = av.y;
        As[lq + 2][lr] = av.z; As[lq + 3][lr] = av.w;
        Bs[lq + 0][lr] = bv.x; Bs[lq + 1][lr] = bv.y;
        Bs[lq + 2][lr] = bv.z; Bs[lq + 3][lr] = bv.w;
        __syncthreads();
        #pragma unroll
        for (int k = 0; k < 16; k++) {
            float4 a = *(const float4*)&As[k][ty * 4];
            ulonglong2 b = *(const ulonglong2*)&Bs[k][tx * 4];
            float ar[4] = {a.x, a.y, a.z, a.w};
            #pragma unroll
            for (int m = 0; m < 4; m++) {
                unsigned long long am = bcast2(ar[m]);
                ffma2(acc2[m][0], am, b.x);
                ffma2(acc2[m][1], am, b.y);
            }
        }
    }
    float* out = outP + (size_t)z * NB * ND;
    #pragma unroll
    for (int a = 0; a < 4; a++) {
        float2 p0 = unpack2(acc2[a][0]);
        float2 p1 = unpack2(acc2[a][1]);
        *(float4*)&out[(size_t)(bm0 + ty * 4 + a) * ND + bn0 + tx * 4] =
            make_float4(p0.x, p0.y, p1.x, p1.y);
    }
}

// ---------------- fused projection reduce: K (slices 0-3) and WV (4-7) ----------------
__global__ void __launch_bounds__(256) proj_reduce(
    const float* __restrict__ part, float* __restrict__ K, float* __restrict__ WV,
    const float* __restrict__ bk, const float* __restrict__ bv)
{
    const int q = blockIdx.x * 256 + threadIdx.x;   // float4 index over 2*32768
    const int MN = NB * ND;
    const int half = (q >= MN / 4);
    const int q2 = half ? q - MN / 4 : q;
    const float* src = part + (size_t)(half ? 4 : 0) * MN;
    float4 s = *(const float4*)&src[q2 * 4];
    #pragma unroll
    for (int z = 1; z < 4; z++) {
        float4 v = *(const float4*)&src[(size_t)z * MN + q2 * 4];
        s.x += v.x; s.y += v.y; s.z += v.z; s.w += v.w;
    }
    const float* bias = half ? bv : bk;
    float4 b = *(const float4*)&bias[(q2 * 4) % ND];
    s.x += b.x; s.y += b.y; s.z += b.z; s.w += b.w;
    float* dst = half ? WV : K;
    *(float4*)&dst[q2 * 4] = s;
}

// ---------------- generic split-K reduce ----------------
__global__ void __launch_bounds__(256) reduce_kernel(
    const float* __restrict__ part, float* __restrict__ C,
    const float* __restrict__ bias, int MN, int N, int Z, int doRelu)
{
    const int q = blockIdx.x * 256 + threadIdx.x;
    if (q * 4 >= MN) return;
    float4 s = *(const float4*)&part[q * 4];
    for (int z = 1; z < Z; z++) {
        float4 v = *(const float4*)&part[(size_t)z * MN + q * 4];
        s.x += v.x; s.y += v.y; s.z += v.z; s.w += v.w;
    }
    if (bias) {
        float4 b = *(const float4*)&bias[(q * 4) % N];
        s.x += b.x; s.y += b.y; s.z += b.z; s.w += b.w;
    }
    if (doRelu) {
        s.x = fmaxf(s.x, 0.f); s.y = fmaxf(s.y, 0.f);
        s.z = fmaxf(s.z, 0.f); s.w = fmaxf(s.w, 0.f);
    }
    *(float4*)&C[q * 4] = s;
}

// ---------------- 64x64 NT GEMM (Gram, single launch) ----------------
__global__ void __launch_bounds__(256) gemm_nt64(
    const float* __restrict__ A, const float* __restrict__ B, float* __restrict__ C,
    int N, int Kd)
{
    __shared__ __align__(16) float As[16][68];
    __shared__ __align__(16) float Bs[16][68];
    const int tid = threadIdx.x;
    const int tx = tid & 15, ty = tid >> 4;
    const int bm0 = blockIdx.y * 64, bn0 = blockIdx.x * 64;
    const int lr = tid >> 2;
    const int lq = (tid & 3) * 4;
    const float* Ap = A + (size_t)(bm0 + lr) * Kd + lq;
    const float* Bp = B + (size_t)(bn0 + lr) * Kd + lq;
    unsigned long long acc2[4][2] = {};
    for (int k0 = 0; k0 < Kd; k0 += 16) {
        float4 av = *(const float4*)(Ap + k0);
        float4 bv = *(const float4*)(Bp + k0);
        __syncthreads();
        As[lq + 0][lr] = av.x; As[lq + 1][lr] = av.y;
        As[lq + 2][lr] = av.z; As[lq + 3][lr] = av.w;
        Bs[lq + 0][lr] = bv.x; Bs[lq + 1][lr] = bv.y;
        Bs[lq + 2][lr] = bv.z; Bs[lq + 3][lr] = bv.w;
        __syncthreads();
        #pragma unroll
        for (int k = 0; k < 16; k++) {
            float4 a = *(const float4*)&As[k][ty * 4];
            ulonglong2 b = *(const ulonglong2*)&Bs[k][tx * 4];
            float ar[4] = {a.x, a.y, a.z, a.w};
            #pragma unroll
            for (int m = 0; m < 4; m++) {
                unsigned long long am = bcast2(ar[m]);
                ffma2(acc2[m][0], am, b.x);
                ffma2(acc2[m][1], am, b.y);
            }
        }
    }
    #pragma unroll
    for (int a = 0; a < 4; a++) {
        float2 p0 = unpack2(acc2[a][0]);
        float2 p1 = unpack2(acc2[a][1]);
        *(float4*)&C[(size_t)(bm0 + ty * 4 + a) * N + bn0 + tx * 4] =
            make_float4(p0.x, p0.y, p1.x, p1.y);
    }
}

// ---------------- 128x128 split-K NT GEMM (packed, double-buffered) ----------------
#define FMA8x8P(kk)                                                             \
    {                                                                           \
        float4 t0 = *(const float4*)&As[buf][kk][ty * 4];                       \
        float4 t1 = *(const float4*)&As[buf][kk][ty * 4 + 64];                  \
        ulonglong2 b01 = *(const ulonglong2*)&Bs[buf][kk][tx * 4];              \
        ulonglong2 b23 = *(const ulonglong2*)&Bs[buf][kk][tx * 4 + 64];         \
        float ar[8] = {t0.x, t0.y, t0.z, t0.w, t1.x, t1.y, t1.z, t1.w};         \
        _Pragma("unroll")                                                       \
        for (int m = 0; m < 8; m++) {                                           \
            unsigned long long am = bcast2(ar[m]);                              \
            ffma2(acc2[m][0], am, b01.x);                                       \
            ffma2(acc2[m][1], am, b01.y);                                       \
            ffma2(acc2[m][2], am, b23.x);                                       \
            ffma2(acc2[m][3], am, b23.y);                                       \
        }                                                                       \
    }

__global__ void __launch_bounds__(256) splitk_nt128(
    const float* __restrict__ A, const float* __restrict__ B, float* __restrict__ outP,
    int N, int ldA, int ldB, int kchunk)
{
    __shared__ __align__(16) float As[2][8][136];
    __shared__ __align__(16) float Bs[2][8][136];
    const int tid = threadIdx.x;
    const int bm0 = blockIdx.y * 128, bn0 = blockIdx.x * 128;
    const int kbase = blockIdx.z * kchunk;
    const int M = gridDim.y * 128;
    const int lr = tid >> 1;
    const int lk = (tid & 1) * 4;
    const float* Ap = A + (size_t)(bm0 + lr) * ldA + kbase + lk;
    const float* Bp = B + (size_t)(bn0 + lr) * ldB + kbase + lk;
    const int tx = tid & 15, ty = tid >> 4;
    unsigned long long acc2[8][4] = {};
    int buf = 0;
    {
        float4 a = *(const float4*)Ap;
        float4 b = *(const float4*)Bp;
        As[0][lk + 0][lr] = a.x; As[0][lk + 1][lr] = a.y;
        As[0][lk + 2][lr] = a.z; As[0][lk + 3][lr] = a.w;
        Bs[0][lk + 0][lr] = b.x; Bs[0][lk + 1][lr] = b.y;
        Bs[0][lk + 2][lr] = b.z; Bs[0][lk + 3][lr] = b.w;
    }
    __syncthreads();
    for (int k0 = 8; k0 <= kchunk; k0 += 8) {
        float4 an, bn;
        if (k0 < kchunk) {
            an = *(const float4*)(Ap + k0);
            bn = *(const float4*)(Bp + k0);
        }
        #pragma unroll
        for (int kk = 0; kk < 8; kk++) FMA8x8P(kk)
        if (k0 < kchunk) {
            buf ^= 1;
            As[buf][lk + 0][lr] = an.x; As[buf][lk + 1][lr] = an.y;
            As[buf][lk + 2][lr] = an.z; As[buf][lk + 3][lr] = an.w;
            Bs[buf][lk + 0][lr] = bn.x; Bs[buf][lk + 1][lr] = bn.y;
            Bs[buf][lk + 2][lr] = bn.z; Bs[buf][lk + 3][lr] = bn.w;
            __syncthreads();
        }
    }
    float* out = outP + (size_t)blockIdx.z * M * N;
    #pragma unroll
    for (int m = 0; m < 8; m++) {
        int r = bm0 + ty * 4 + (m & 3) + (m >> 2) * 64;
        float2 p0 = unpack2(acc2[m][0]);
        float2 p1 = unpack2(acc2[m][1]);
        float2 p2 = unpack2(acc2[m][2]);
        float2 p3 = unpack2(acc2[m][3]);
        *(float4*)&out[(size_t)r * N + bn0 + tx * 4] = make_float4(p0.x, p0.y, p1.x, p1.y);
        *(float4*)&out[(size_t)r * N + bn0 + tx * 4 + 64] = make_float4(p2.x, p2.y, p3.x, p3.y);
    }
}

// ---------------- prep: max pass, probe-threshold counts (no atomics), compaction ----------------
__global__ void __launch_bounds__(256) prep_kernel()
{
    const int i = blockIdx.x;
    const int tid = threadIdx.x;
    const int lane = tid & 31, wid = tid >> 5;
    __shared__ float red[256];
    __shared__ unsigned int s6[8][6];
    __shared__ unsigned int tots[6];
    __shared__ unsigned int winc[8];
    const float4* row4 = (const float4*)(g_E + (size_t)i * NS);
    // pass 1: row max
    float mx = -1e30f;
    for (int q = tid; q < NS / 4; q += 256) {
        float4 v = row4[q];
        mx = fmaxf(mx, fmaxf(fmaxf(v.x, v.y), fmaxf(v.z, v.w)));
    }
    red[tid] = mx;
    __syncthreads();
    for (int s = 128; s; s >>= 1) {
        if (tid < s) red[tid] = fmaxf(red[tid], red[tid + s]);
        __syncthreads();
    }
    const float m = red[0];
    __syncthreads();
    if (tid == 0) g_m[i] = m;
    // pass 2: probe counts over per-thread segment
    const float thr0 = m - 20.f, thr1p = m - 24.f, thr2p = m - 28.f;
    const float thr3p = m - 32.f, thr4p = m - 40.f, thr5p = m - 60.f;
    const float* erow = g_E + (size_t)i * NS;
    const int base = tid * SEG;
    unsigned int c0 = 0, c1 = 0, c2 = 0, c3 = 0, c4 = 0, c5 = 0;
    for (int k = 0; k < SEG; k += 4) {
        float4 v = *(const float4*)(erow + base + k);
        float vv[4] = {v.x, v.y, v.z, v.w};
        #pragma unroll
        for (int u = 0; u < 4; u++) {
            c0 += (vv[u] >= thr0); c1 += (vv[u] >= thr1p); c2 += (vv[u] >= thr2p);
            c3 += (vv[u] >= thr3p); c4 += (vv[u] >= thr4p); c5 += (vv[u] >= thr5p);
        }
    }
    unsigned int cs[6] = {c0, c1, c2, c3, c4, c5};
    #pragma unroll
    for (int p = 0; p < 6; p++) {
        unsigned int w = cs[p];
        #pragma unroll
        for (int off = 16; off; off >>= 1) w += __shfl_down_sync(0xffffffffu, w, off);
        if (lane == 0) s6[wid][p] = w;
    }
    __syncthreads();
    if (tid < 6) {
        unsigned int t = 0;
        #pragma unroll
        for (int w = 0; w < 8; w++) t += s6[w][tid];
        tots[tid] = t;
    }
    __syncthreads();
    // pick shallowest probe with >=256 candidates
    int pstar = 5;
    #pragma unroll
    for (int p = 5; p >= 0; p--) if (tots[p] >= 256u) pstar = p;
    const float tsel = (pstar == 0) ? thr0 : (pstar == 1) ? thr1p : (pstar == 2) ? thr2p
                     : (pstar == 3) ? thr3p : (pstar == 4) ? thr4p : thr5p;
    unsigned int myc1 = (pstar == 0) ? c0 : (pstar == 1) ? c1 : (pstar == 2) ? c2
                      : (pstar == 3) ? c3 : (pstar == 4) ? c4 : c5;
    // block scan of pack = cand_count | (rcand_count << 16)
    unsigned int pack = myc1 | (c0 << 16);
    unsigned int x = pack;
    #pragma unroll
    for (int off = 1; off < 32; off <<= 1) {
        unsigned int y = __shfl_up_sync(0xffffffffu, x, off);
        if (lane >= off) x += y;
    }
    if (lane == 31) winc[wid] = x;
    __syncthreads();
    if (tid < 8) {
        unsigned int xx = winc[tid];
        #pragma unroll
        for (int off = 1; off < 8; off <<= 1) {
            unsigned int y = __shfl_up_sync(0xffu, xx, off);
            if (tid >= off) xx += y;
        }
        winc[tid] = xx;
    }
    __syncthreads();
    unsigned int wb = (wid == 0) ? 0u : winc[wid - 1];
    unsigned int excl = x - pack + wb;
    int o1 = (int)(excl & 0xffffu);
    int o2 = (int)(excl >> 16);
    unsigned long long* cd = g_cand + (size_t)i * CMAX;
    unsigned int* rd = g_rcand + (size_t)i * RC;
    for (int k = 0; k < SEG; k += 4) {
        float4 v = *(const float4*)(erow + base + k);
        float vv[4] = {v.x, v.y, v.z, v.w};
        #pragma unroll
        for (int u = 0; u < 4; u++) {
            const int j = base + k + u;
            if (vv[u] >= tsel) {
                if (o1 < CMAX)
                    cd[o1] = ((unsigned long long)fkey(vv[u]) << 32) | (unsigned int)(~j);
                o1++;
            }
            if (vv[u] >= thr0) {
                if (o2 < RC) rd[o2] = (unsigned int)j;
                o2++;
            }
        }
    }
    if (tid == 0) {
        int n1 = (int)tots[pstar];
        int n2 = (int)tots[0];
        g_cand_n[i] = n1 < CMAX ? n1 : CMAX;
        g_rcand_n[i] = n2 < RC ? n2 : RC;
    }
}

// ---------------- sequential argmax chain: single warp ----------------
__global__ void __launch_bounds__(32) seq_kernel()
{
    __shared__ unsigned int mask[NS / 32];
    __shared__ unsigned long long cbuf[2][CCAP];
    __shared__ float grow[2][NB];
    __shared__ int cnArr[NB];
    __shared__ int slotArr[NB];
    __shared__ int writerArr[NB];
    const int lane = threadIdx.x;
    for (int q = lane; q < NS / 32; q += 32) mask[q] = 0u;
    for (int q = lane; q < NB; q += 32) cnArr[q] = g_cand_n[q];
    __syncwarp();
    int cnt = 0;
    {
        int lim = cnArr[0] < CCAP ? cnArr[0] : CCAP;
        for (int q = lane; q < lim; q += 32) cbuf[0][q] = g_cand[q];
        for (int q = lane; q < NB; q += 32) grow[0][q] = g_G[q];
    }
    __syncwarp();
    for (int i = 0; i < NB; i++) {
        const int buf = i & 1, nxt = buf ^ 1;
        unsigned long long pc[CCAP / 32];
        float pg[NB / 32];
        int limN = 0;
        if (i + 1 < NB) {
            int cnN = cnArr[i + 1];
            limN = cnN < CCAP ? cnN : CCAP;
            #pragma unroll
            for (int k = 0; k < NB / 32; k++)
                pg[k] = g_G[(i + 1) * NB + lane + k * 32];
            #pragma unroll
            for (int k = 0; k < CCAP / 32; k++) {
                int idx = lane + k * 32;
                pc[k] = (idx < limN) ? g_cand[(size_t)(i + 1) * CMAX + idx] : 0ull;
            }
        }
        const int cn = cnArr[i];
        unsigned long long best = 0ull;
        for (int q = lane; q < cn; q += 32) {
            unsigned long long p = (q < CCAP) ? cbuf[buf][q]
                                              : g_cand[(size_t)i * CMAX + q];
            unsigned int idx = ~(unsigned int)p;
            if (!((mask[idx >> 5] >> (idx & 31)) & 1u))
                best = best > p ? best : p;
        }
        for (int t = lane; t < cnt; t += 32) {
            float g = grow[buf][writerArr[t]];
            unsigned long long p =
                ((unsigned long long)fkey(g) << 32) | (unsigned int)(~slotArr[t]);
            best = best > p ? best : p;
        }
        #pragma unroll
        for (int off = 16; off; off >>= 1) {
            unsigned long long o = __shfl_down_sync(0xffffffffu, best, off);
            best = best > o ? best : o;
        }
        best = __shfl_sync(0xffffffffu, best, 0);
        const int sb = (int)(~(unsigned int)best);
        int found = -1;
        for (int t = lane; t < cnt; t += 32)
            if (slotArr[t] == sb) found = t;
        #pragma unroll
        for (int off = 16; off; off >>= 1) {
            int o = __shfl_down_sync(0xffffffffu, found, off);
            found = found > o ? found : o;
        }
        found = __shfl_sync(0xffffffffu, found, 0);
        if (lane == 0) {
            g_slots[i] = sb;
            if (found >= 0) writerArr[found] = i;
            else { slotArr[cnt] = sb; writerArr[cnt] = i; }
            mask[sb >> 5] |= (1u << (sb & 31));
        }
        if (found < 0) cnt++;
        if (i + 1 < NB) {
            #pragma unroll
            for (int k = 0; k < NB / 32; k++)
                grow[nxt][lane + k * 32] = pg[k];
            #pragma unroll
            for (int k = 0; k < CCAP / 32; k++) {
                int idx = lane + k * 32;
                if (idx < limN) cbuf[nxt][idx] = pc[k];
            }
        }
        __syncwarp();
    }
}

// ---------------- passB: sparse softmax + corrections + merge ----------------
__global__ void __launch_bounds__(512) passB_kernel(const float* __restrict__ S,
                                                    const float* __restrict__ MV)
{
    const int i = blockIdx.x;
    const int tid = threadIdx.x;
    __shared__ int sl[NB];
    __shared__ float e0s[NB], e1s[NB], zar[NB];
    __shared__ unsigned char lastf[NB];
    __shared__ unsigned int sidx[512];
    __shared__ float sw[512];
    __shared__ float zred[512];
    if (tid < NB) sl[tid] = g_slots[tid];
    __syncthreads();
    const float mi = g_m[i];
    const float* Erow = g_E + (size_t)i * NS;
    if (tid < NB) {
        float z = 0.f;
        unsigned char lf = 0;
        if (tid < i) {
            const int t = tid;
            const int s = sl[t];
            bool last = true;
            for (int t2 = t + 1; t2 < i; t2++)
                if (sl[t2] == s) { last = false; break; }
            if (last) {
                lf = 1;
                const float e0 = __expf(Erow[s] - mi);
                const float e1 = __expf(g_G[i * NB + t] - mi);
                e0s[t] = e0; e1s[t] = e1;
                z = e1 - e0;
            }
        }
        lastf[tid] = lf;
        zar[tid] = z;
    }
    __syncthreads();
    for (int s = 128; s; s >>= 1) {
        if (tid < s) zar[tid] += zar[tid + s];
        __syncthreads();
    }
    const float zcorr = zar[0];
    const int d = tid;
    const int rn = g_rcand_n[i];
    const unsigned int* rlist = g_rcand + (size_t)i * RC;
    float a0 = 0.f, a1 = 0.f, a2 = 0.f, a3 = 0.f;
    float zacc = 0.f;
    for (int st = 0; st < rn; st += 512) {
        const int nst = (rn - st) < 512 ? (rn - st) : 512;
        __syncthreads();
        if (tid < nst) {
            unsigned int j = rlist[st + tid];
            float w = __expf(Erow[j] - mi);
            sidx[tid] = j;
            sw[tid] = w;
            zacc += w;
        }
        __syncthreads();
        int t = 0;
        for (; t + 4 <= nst; t += 4) {
            a0 += sw[t + 0] * MV[(size_t)sidx[t + 0] * ND + d];
            a1 += sw[t + 1] * MV[(size_t)sidx[t + 1] * ND + d];
            a2 += sw[t + 2] * MV[(size_t)sidx[t + 2] * ND + d];
            a3 += sw[t + 3] * MV[(size_t)sidx[t + 3] * ND + d];
        }
        for (; t < nst; t++)
            a0 += sw[t] * MV[(size_t)sidx[t] * ND + d];
    }
    zred[tid] = zacc;
    __syncthreads();
    for (int s = 256; s; s >>= 1) {
        if (tid < s) zred[tid] += zred[tid + s];
        __syncthreads();
    }
    const float Z = zred[0] + zcorr;
    float r = (a0 + a1) + (a2 + a3);
    for (int t = 0; t < i; t++) {
        if (lastf[t]) {
            r += e1s[t] * g_WV[(size_t)t * ND + d] - e0s[t] * MV[(size_t)sl[t] * ND + d];
        }
    }
    g_merged[(size_t)i * (2 * ND) + d] = S[(size_t)i * ND + d];
    g_merged[(size_t)i * (2 * ND) + ND + d] = r / Z;
}

// ---------------- launch ----------------
extern "C" void kernel_launch(void* const* d_in, const int* in_sizes, int n_in,
                              void* d_out, int out_size)
{
    (void)in_sizes; (void)n_in; (void)out_size;
    const float* S  = (const float*)d_in[0];
    const float* MK = (const float*)d_in[1];
    const float* MV = (const float*)d_in[2];
    const float* Wk = (const float*)d_in[3];
    const float* bk = (const float*)d_in[4];
    const float* Wv = (const float*)d_in[5];
    const float* bv = (const float*)d_in[6];
    const float* W1 = (const float*)d_in[7];
    const float* b1 = (const float*)d_in[8];
    const float* W2 = (const float*)d_in[9];
    const float* b2 = (const float*)d_in[10];
    float* out = (float*)d_out;

    float *pK, *pWV, *pG, *pE, *pMerged, *pH1, *pPart;
    cudaGetSymbolAddress((void**)&pK, g_K);
    cudaGetSymbolAddress((void**)&pWV, g_WV);
    cudaGetSymbolAddress((void**)&pG, g_G);
    cudaGetSymbolAddress((void**)&pE, g_E);
    cudaGetSymbolAddress((void**)&pMerged, g_merged);
    cudaGetSymbolAddress((void**)&pH1, g_H1);
    cudaGetSymbolAddress((void**)&pPart, g_part);

    const dim3 blk(256);
    const int MN_KD = NB * ND;      // 131072
    // 0: fused projections (K + WV partials)
    proj_split<<<dim3(ND / 64, NB / 64, 8), blk>>>(S, Wk, Wv, pPart);
    // 1: fused projection reduce
    proj_reduce<<<(2 * MN_KD) / 1024, blk>>>(pPart, pK, pWV, bk, bv);
    // 2: base scores E (128-tile, no split)
    splitk_nt128<<<dim3(NS / 128, NB / 128, 1), blk>>>(pK, MK, pE, NS, ND, ND, ND);
    // 3: prep (probe thresholds, no atomics)
    prep_kernel<<<NB, 256>>>();
    // 4: Gram (single launch)
    gemm_nt64<<<dim3(NB / 64, NB / 64), blk>>>(pK, pK, pG, NB, ND);
    // 5: sequential argmax chain  <-- ncu capture slot
    seq_kernel<<<1, 32>>>();
    // 6: passB
    passB_kernel<<<NB, 512>>>(S, MV);
    // 7-8: MLP layer 1 (128-tile split-K=4)
    splitk_nt128<<<dim3(NH / 128, NB / 128, 4), blk>>>(pMerged, W1, pPart, NH, 2 * ND, 2 * ND, 256);
    reduce_kernel<<<(NB * NH) / 1024, blk>>>(pPart, pH1, b1, NB * NH, NH, 4, 1);
    // 9-10: MLP layer 2 (128-tile split-K=16)
    splitk_nt128<<<dim3(ND / 128, NB / 128, 16), blk>>>(pH1, W2, pPart, ND, NH, NH, 128);
    reduce_kernel<<<MN_KD / 1024, blk>>>(pPart, out, b2, MN_KD, ND, 16, 0);
}